// round 1
// baseline (speedup 1.0000x reference)
#include <cuda_runtime.h>
#include <cuda_bf16.h>
#include <math.h>

// ---------------------------------------------------------------------------
// VisionAttention: x[2048,1280] -> QKV gemm -> RoPE -> block-diag attention
// (8 segments of 256) -> out gemm. All fp32 baseline.
// ---------------------------------------------------------------------------

#define S_LEN 2048
#define HID   1280
#define NHEAD 16
#define HDIM  80
#define QKV_N (3 * HID)   // 3840
#define SEG   256
#define NSEG  8

// scratch (device globals: no allocation allowed in kernel_launch)
__device__ float g_qkv[S_LEN * QKV_N];     // 2048 x 3840
__device__ float g_attn[S_LEN * HID];      // 2048 x 1280

// ---------------------------------------------------------------------------
// Classic 128x128x16 register-tiled SGEMM with bias.
// A: MxK row-major, B: KxN row-major, C: MxN row-major. 256 threads.
// ---------------------------------------------------------------------------
#define BM 128
#define BN 128
#define BK 16
#define TM 8
#define TN 8

__global__ __launch_bounds__(256, 2)
void sgemm_bias_kernel(int M, int N, int K,
                       const float* __restrict__ A,
                       const float* __restrict__ B,
                       const float* __restrict__ bias,
                       float* __restrict__ C) {
    __shared__ float As[BK][BM];   // A stored transposed
    __shared__ float Bs[BK][BN];

    const int tid  = threadIdx.x;
    const int bcol = blockIdx.x;   // N tile
    const int brow = blockIdx.y;   // M tile

    const int tx = tid % 16;       // 16x16 thread grid
    const int ty = tid / 16;

    // A load mapping: 128 rows x 16 cols, float4 per thread x2
    const int aRow = tid >> 2;             // 0..63
    const int aCol = (tid & 3) * 4;        // 0,4,8,12
    // B load mapping: 16 rows x 128 cols
    const int bRow = tid >> 5;             // 0..7
    const int bCol = (tid & 31) * 4;       // 0..124

    float acc[TM][TN];
#pragma unroll
    for (int i = 0; i < TM; i++)
#pragma unroll
        for (int j = 0; j < TN; j++) acc[i][j] = 0.f;

    float regA[TM], regB[TN];

    const float* Abase = A + (size_t)(brow * BM) * K;
    const float* Bbase = B + bcol * BN;

    for (int kt = 0; kt < K; kt += BK) {
#pragma unroll
        for (int i = 0; i < 2; i++) {
            int r = aRow + i * 64;
            float4 v = *(const float4*)&Abase[(size_t)r * K + kt + aCol];
            As[aCol + 0][r] = v.x;
            As[aCol + 1][r] = v.y;
            As[aCol + 2][r] = v.z;
            As[aCol + 3][r] = v.w;
        }
#pragma unroll
        for (int i = 0; i < 2; i++) {
            int r = bRow + i * 8;
            float4 v = *(const float4*)&Bbase[(size_t)(kt + r) * N + bCol];
            *(float4*)&Bs[r][bCol] = v;
        }
        __syncthreads();

#pragma unroll
        for (int k = 0; k < BK; k++) {
#pragma unroll
            for (int i = 0; i < TM; i++) regA[i] = As[k][ty * TM + i];
#pragma unroll
            for (int j = 0; j < TN; j++) regB[j] = Bs[k][tx * TN + j];
#pragma unroll
            for (int i = 0; i < TM; i++)
#pragma unroll
                for (int j = 0; j < TN; j++)
                    acc[i][j] += regA[i] * regB[j];
        }
        __syncthreads();
    }

#pragma unroll
    for (int i = 0; i < TM; i++) {
        int row = brow * BM + ty * TM + i;
        int colb = bcol * BN + tx * TN;
#pragma unroll
        for (int j4 = 0; j4 < 2; j4++) {
            float4 o;
            o.x = acc[i][j4 * 4 + 0] + bias[colb + j4 * 4 + 0];
            o.y = acc[i][j4 * 4 + 1] + bias[colb + j4 * 4 + 1];
            o.z = acc[i][j4 * 4 + 2] + bias[colb + j4 * 4 + 2];
            o.w = acc[i][j4 * 4 + 3] + bias[colb + j4 * 4 + 3];
            *(float4*)&C[(size_t)row * N + colb + j4 * 4] = o;
        }
    }
}

// ---------------------------------------------------------------------------
// RoPE on q,k halves of qkv (in place, pair-safe), folds q scale.
// One thread per (s, h, d<40) pair; handles both q and k.
// ---------------------------------------------------------------------------
__global__ void rope_kernel(float* __restrict__ qkv,
                            const float* __restrict__ cosb,
                            const float* __restrict__ sinb) {
    int idx = blockIdx.x * blockDim.x + threadIdx.x;
    const int total = S_LEN * NHEAD * (HDIM / 2);
    if (idx >= total) return;
    int s   = idx / (NHEAD * (HDIM / 2));
    int rem = idx % (NHEAD * (HDIM / 2));
    int h   = rem / (HDIM / 2);
    int d   = rem % (HDIM / 2);          // 0..39

    const float scale = rsqrtf((float)HDIM);

    float c1 = cosb[s * HDIM + d];
    float s1 = sinb[s * HDIM + d];
    float c2 = cosb[s * HDIM + d + 40];
    float s2 = sinb[s * HDIM + d + 40];

    size_t base = (size_t)s * QKV_N + h * HDIM + d;
    // q
    float q1 = qkv[base];
    float q2 = qkv[base + 40];
    qkv[base]      = (q1 * c1 - q2 * s1) * scale;
    qkv[base + 40] = (q2 * c2 + q1 * s2) * scale;
    // k
    float k1 = qkv[base + HID];
    float k2 = qkv[base + HID + 40];
    qkv[base + HID]      = k1 * c1 - k2 * s1;
    qkv[base + HID + 40] = k2 * c2 + k1 * s2;
}

// ---------------------------------------------------------------------------
// Block-diagonal attention. grid = (4 qtiles, 8 segments, 16 heads).
// Each block: Q tile 64x80, K/V 256x80 in smem (V reuses K buffer),
// scores 64x256 in smem. 256 threads.
// Padded strides for conflict-free smem access.
// ---------------------------------------------------------------------------
#define QT     64
#define SQ_LD  81     // Q/K/V row stride
#define SS_LD  257    // scores row stride
#define ATTN_SMEM ((QT*SQ_LD + SEG*SQ_LD + QT*SS_LD) * 4)

__global__ __launch_bounds__(256, 1)
void attn_kernel(const float* __restrict__ qkv,
                 const int* __restrict__ cu,
                 float* __restrict__ out) {
    extern __shared__ float sm[];
    float* sQ = sm;                       // [64][81]
    float* sK = sQ + QT * SQ_LD;          // [256][81]  (later reused for V)
    float* sS = sK + SEG * SQ_LD;         // [64][257]

    const int tid  = threadIdx.x;
    const int qt   = blockIdx.x;
    const int seg  = blockIdx.y;
    const int head = blockIdx.z;

    const int segStart = cu[seg];
    const int q0 = segStart + qt * QT;

    // load Q tile
    for (int i = tid; i < QT * HDIM; i += 256) {
        int r = i / HDIM, d = i % HDIM;
        sQ[r * SQ_LD + d] = qkv[(size_t)(q0 + r) * QKV_N + head * HDIM + d];
    }
    // load K tile
    for (int i = tid; i < SEG * HDIM; i += 256) {
        int r = i / HDIM, d = i % HDIM;
        sK[r * SQ_LD + d] = qkv[(size_t)(segStart + r) * QKV_N + HID + head * HDIM + d];
    }
    __syncthreads();

    // ---- phase 1: scores = Q @ K^T  (micro-tile 4 rows x 16 strided cols)
    const int ti = tid >> 4;      // 0..15 -> rows ti*4..ti*4+3
    const int tj = tid & 15;      // 0..15 -> cols tj + 16*b

    {
        float acc[4][16];
#pragma unroll
        for (int a = 0; a < 4; a++)
#pragma unroll
            for (int b = 0; b < 16; b++) acc[a][b] = 0.f;

        for (int d = 0; d < HDIM; d++) {
            float qr[4];
#pragma unroll
            for (int a = 0; a < 4; a++) qr[a] = sQ[(ti * 4 + a) * SQ_LD + d];
            float kr[16];
#pragma unroll
            for (int b = 0; b < 16; b++) kr[b] = sK[(tj + 16 * b) * SQ_LD + d];
#pragma unroll
            for (int a = 0; a < 4; a++)
#pragma unroll
                for (int b = 0; b < 16; b++) acc[a][b] += qr[a] * kr[b];
        }
#pragma unroll
        for (int a = 0; a < 4; a++)
#pragma unroll
            for (int b = 0; b < 16; b++)
                sS[(ti * 4 + a) * SS_LD + tj + 16 * b] = acc[a][b];
    }
    __syncthreads();

    // ---- reload V into the K buffer (overlaps with softmax below)
    for (int i = tid; i < SEG * HDIM; i += 256) {
        int r = i / HDIM, d = i % HDIM;
        sK[r * SQ_LD + d] = qkv[(size_t)(segStart + r) * QKV_N + 2 * HID + head * HDIM + d];
    }

    // ---- softmax over rows: 4 lanes per row, 64 strided cols each
    {
        const int r  = tid >> 2;   // 0..63
        const int cl = tid & 3;    // 0..3
        float mx = -1e30f;
#pragma unroll
        for (int j = 0; j < 64; j++) {
            float v = sS[r * SS_LD + cl + 4 * j];
            mx = fmaxf(mx, v);
        }
        mx = fmaxf(mx, __shfl_xor_sync(0xFFFFFFFFu, mx, 1));
        mx = fmaxf(mx, __shfl_xor_sync(0xFFFFFFFFu, mx, 2));
        float sum = 0.f;
#pragma unroll
        for (int j = 0; j < 64; j++) {
            int c = cl + 4 * j;
            float e = __expf(sS[r * SS_LD + c] - mx);
            sS[r * SS_LD + c] = e;
            sum += e;
        }
        sum += __shfl_xor_sync(0xFFFFFFFFu, sum, 1);
        sum += __shfl_xor_sync(0xFFFFFFFFu, sum, 2);
        float inv = 1.f / sum;
#pragma unroll
        for (int j = 0; j < 64; j++) sS[r * SS_LD + cl + 4 * j] *= inv;
    }
    __syncthreads();

    // ---- phase 2: out = W @ V  (micro-tile 4 rows x 5 strided dims)
    {
        float acc[4][5];
#pragma unroll
        for (int a = 0; a < 4; a++)
#pragma unroll
            for (int u = 0; u < 5; u++) acc[a][u] = 0.f;

        for (int c = 0; c < SEG; c++) {
            float wv[4];
#pragma unroll
            for (int a = 0; a < 4; a++) wv[a] = sS[(ti * 4 + a) * SS_LD + c];
            float vr[5];
#pragma unroll
            for (int u = 0; u < 5; u++) vr[u] = sK[c * SQ_LD + tj + 16 * u];
#pragma unroll
            for (int a = 0; a < 4; a++)
#pragma unroll
                for (int u = 0; u < 5; u++) acc[a][u] += wv[a] * vr[u];
        }
#pragma unroll
        for (int a = 0; a < 4; a++) {
            int row = q0 + ti * 4 + a;
#pragma unroll
            for (int u = 0; u < 5; u++) {
                int d = tj + 16 * u;
                out[(size_t)row * HID + head * HDIM + d] = acc[a][u];
            }
        }
    }
}

// ---------------------------------------------------------------------------
extern "C" void kernel_launch(void* const* d_in, const int* in_sizes, int n_in,
                              void* d_out, int out_size) {
    const float* x      = (const float*)d_in[0];
    const float* cosb   = (const float*)d_in[1];
    const float* sinb   = (const float*)d_in[2];
    const float* W_qkv  = (const float*)d_in[3];
    const float* b_qkv  = (const float*)d_in[4];
    const float* W_out  = (const float*)d_in[5];
    const float* b_out  = (const float*)d_in[6];
    const int*   cu     = (const int*)d_in[7];
    float*       outp   = (float*)d_out;

    float* qkv;  cudaGetSymbolAddress((void**)&qkv,  g_qkv);
    float* attn; cudaGetSymbolAddress((void**)&attn, g_attn);

    static bool attr_set = false;
    if (!attr_set) {
        cudaFuncSetAttribute(attn_kernel,
                             cudaFuncAttributeMaxDynamicSharedMemorySize,
                             ATTN_SMEM);
        attr_set = true;
    }

    // 1. QKV projection: [2048,1280] @ [1280,3840] + b
    {
        dim3 grid(QKV_N / BN, S_LEN / BM);
        sgemm_bias_kernel<<<grid, 256>>>(S_LEN, QKV_N, HID, x, W_qkv, b_qkv, qkv);
    }
    // 2. RoPE (+ fold q scale)
    {
        int total = S_LEN * NHEAD * (HDIM / 2);
        rope_kernel<<<(total + 255) / 256, 256>>>(qkv, cosb, sinb);
    }
    // 3. Block-diagonal attention
    {
        dim3 grid(SEG / QT, NSEG, NHEAD);
        attn_kernel<<<grid, 256, ATTN_SMEM>>>(qkv, cu, attn);
    }
    // 4. Output projection: [2048,1280] @ [1280,1280] + b
    {
        dim3 grid(HID / BN, S_LEN / BM);
        sgemm_bias_kernel<<<grid, 256>>>(S_LEN, HID, HID, attn, W_out, b_out, outp);
    }
}

// round 3
// speedup vs baseline: 1.7451x; 1.7451x over previous
#include <cuda_runtime.h>
#include <cuda_bf16.h>
#include <cstdint>
#include <math.h>

// ===========================================================================
// VisionAttention on GB300 (sm_103 base target):
//   bf16-split mma.sync GEMMs (HMMA) + fp32 block-diag attention
// ===========================================================================

#define S_LEN 2048
#define HID   1280
#define NHEAD 16
#define HDIM  80
#define QKV_N (3 * HID)   // 3840
#define SEG   256
#define NSEG  8

// ---------------- device scratch (no allocations allowed) ------------------
__device__ __align__(256) float g_qkv[S_LEN * QKV_N];
__device__ __align__(256) float g_attn[S_LEN * HID];
__device__ __align__(256) __nv_bfloat16 g_xh[S_LEN * HID];
__device__ __align__(256) __nv_bfloat16 g_xl[S_LEN * HID];
__device__ __align__(256) __nv_bfloat16 g_ah[S_LEN * HID];
__device__ __align__(256) __nv_bfloat16 g_al[S_LEN * HID];
__device__ __align__(256) __nv_bfloat16 g_wqh[QKV_N * HID];  // [N=3840][K=1280]
__device__ __align__(256) __nv_bfloat16 g_wql[QKV_N * HID];
__device__ __align__(256) __nv_bfloat16 g_woh[HID * HID];    // [N=1280][K=1280]
__device__ __align__(256) __nv_bfloat16 g_wol[HID * HID];

__device__ __forceinline__ uint32_t smem_to_u32(const void* p) {
    uint32_t a;
    asm("{ .reg .u64 t; cvta.to.shared.u64 t, %1; cvt.u32.u64 %0, t; }"
        : "=r"(a) : "l"(p));
    return a;
}

#define CP_ASYNC16(sa, gp) \
    asm volatile("cp.async.cg.shared.global [%0], [%1], 16;" \
        :: "r"(sa), "l"(gp) : "memory")
#define CP_COMMIT() asm volatile("cp.async.commit_group;" ::: "memory")

#define MMA_BF16(ac, a, b) \
    asm volatile("mma.sync.aligned.m16n8k16.row.col.f32.bf16.bf16.f32 " \
        "{%0,%1,%2,%3},{%4,%5,%6,%7},{%8,%9},{%0,%1,%2,%3};" \
        : "+f"((ac)[0]), "+f"((ac)[1]), "+f"((ac)[2]), "+f"((ac)[3]) \
        : "r"((a)[0]), "r"((a)[1]), "r"((a)[2]), "r"((a)[3]), \
          "r"((b)[0]), "r"((b)[1]))

#define LDS32(dst, addr) \
    asm volatile("ld.shared.b32 %0, [%1];" : "=r"(dst) : "r"(addr))

// ---------------------------------------------------------------------------
// Prep: fp32 -> (hi, lo) bf16 split; tiled transpose+split for weights
// ---------------------------------------------------------------------------
__global__ void split_kernel(const float* __restrict__ src,
                             __nv_bfloat16* __restrict__ hi,
                             __nv_bfloat16* __restrict__ lo, int n) {
    int i = blockIdx.x * blockDim.x + threadIdx.x;
    if (i >= n) return;
    float a = src[i];
    __nv_bfloat16 h = __float2bfloat16(a);
    hi[i] = h;
    lo[i] = __float2bfloat16(a - __bfloat162float(h));
}

// W [K][N] row-major fp32 -> Th, Tl [N][K] bf16
__global__ void transpose_split_kernel(const float* __restrict__ W,
                                       __nv_bfloat16* __restrict__ Th,
                                       __nv_bfloat16* __restrict__ Tl,
                                       int K, int N) {
    __shared__ float t[32][33];
    int bn = blockIdx.x, bk = blockIdx.y;
    int tx = threadIdx.x, ty = threadIdx.y;   // 32 x 8
#pragma unroll
    for (int i = 0; i < 4; i++)
        t[ty + i * 8][tx] = W[(size_t)(bk * 32 + ty + i * 8) * N + bn * 32 + tx];
    __syncthreads();
#pragma unroll
    for (int i = 0; i < 4; i++) {
        float a = t[tx][ty + i * 8];
        __nv_bfloat16 h = __float2bfloat16(a);
        size_t o = (size_t)(bn * 32 + ty + i * 8) * K + bk * 32 + tx;
        Th[o] = h;
        Tl[o] = __float2bfloat16(a - __bfloat162float(h));
    }
}

// ---------------------------------------------------------------------------
// bf16-split GEMM via mma.sync: C[M,N] = (Ah+Al)@(Bh+Bl)^T + bias
// B given as [N][K]. 128x128 CTA tile, 8 warps x (64x32), BK=32,
// double-buffered cp.async. Padded smem rows (80B) -> conflict-free LDS.
// ---------------------------------------------------------------------------
#define GBK        32
#define ROW_B      80                       // bytes per smem row (32 bf16 + pad)
#define TILE_B     (128 * ROW_B)            // 10240 B per operand tile
#define STAGE_B    (4 * TILE_B)             // Ah, Al, Bh, Bl
#define G_SMEM     (2 * STAGE_B)            // 81920 B

__global__ __launch_bounds__(256)
void gemm_bf16x3_kernel(int M, int N, int K,
                        const __nv_bfloat16* __restrict__ Ah,
                        const __nv_bfloat16* __restrict__ Al,
                        const __nv_bfloat16* __restrict__ Bh,
                        const __nv_bfloat16* __restrict__ Bl,
                        const float* __restrict__ bias,
                        float* __restrict__ C) {
    extern __shared__ __align__(16) char smem[];
    const uint32_t sbase = smem_to_u32(smem);

    const int tid  = threadIdx.x;
    const int wid  = tid >> 5;
    const int lane = tid & 31;
    const int g    = lane >> 2;       // groupID 0..7
    const int tig  = lane & 3;        // thread-in-group
    const int wm   = wid & 1;         // warp row (64 rows each)
    const int wn   = wid >> 1;        // warp col (32 cols each)
    const int n0   = blockIdx.x * 128;
    const int m0   = blockIdx.y * 128;

    const __nv_bfloat16* srcs[4] = {
        Ah + (size_t)m0 * K, Al + (size_t)m0 * K,
        Bh + (size_t)n0 * K, Bl + (size_t)n0 * K };

    float acc[4][4][4];
#pragma unroll
    for (int i = 0; i < 4; i++)
#pragma unroll
        for (int j = 0; j < 4; j++)
#pragma unroll
            for (int r = 0; r < 4; r++) acc[i][j][r] = 0.f;

    const int KT = K / GBK;

    // ---- stage copy: 4 tiles x 128 rows x 64B = 2048 x 16B chunks
    auto issue_stage = [&](int buf, int kt) {
#pragma unroll
        for (int i = 0; i < 8; i++) {
            int c    = tid + i * 256;
            int tile = c >> 9;
            int rem  = c & 511;
            int row  = rem >> 2;
            int c16  = rem & 3;
            const __nv_bfloat16* gp = srcs[tile] + (size_t)row * K + kt * GBK + c16 * 8;
            uint32_t sa = sbase + buf * STAGE_B + tile * TILE_B + row * ROW_B + c16 * 16;
            CP_ASYNC16(sa, gp);
        }
        CP_COMMIT();
    };

    issue_stage(0, 0);

    for (int kt = 0; kt < KT; kt++) {
        const int buf = kt & 1;
        if (kt + 1 < KT) {
            issue_stage(buf ^ 1, kt + 1);
            asm volatile("cp.async.wait_group 1;" ::: "memory");
        } else {
            asm volatile("cp.async.wait_group 0;" ::: "memory");
        }
        __syncthreads();

        const uint32_t sAh = sbase + buf * STAGE_B;
        const uint32_t sAl = sAh + TILE_B;
        const uint32_t sBh = sAh + 2 * TILE_B;
        const uint32_t sBl = sAh + 3 * TILE_B;

#pragma unroll
        for (int ks = 0; ks < 2; ks++) {
            uint32_t bh[4][2], bl[4][2];
#pragma unroll
            for (int nt = 0; nt < 4; nt++) {
                uint32_t ro = (uint32_t)(wn * 32 + nt * 8 + g) * ROW_B + ks * 32 + tig * 4;
                LDS32(bh[nt][0], sBh + ro);
                LDS32(bh[nt][1], sBh + ro + 16);
                LDS32(bl[nt][0], sBl + ro);
                LDS32(bl[nt][1], sBl + ro + 16);
            }
            uint32_t ah[4][4], al[4][4];
#pragma unroll
            for (int mt = 0; mt < 4; mt++) {
                uint32_t r0 = (uint32_t)(wm * 64 + mt * 16 + g) * ROW_B + ks * 32 + tig * 4;
                uint32_t r1 = r0 + 8 * ROW_B;
                LDS32(ah[mt][0], sAh + r0);
                LDS32(ah[mt][1], sAh + r1);
                LDS32(ah[mt][2], sAh + r0 + 16);
                LDS32(ah[mt][3], sAh + r1 + 16);
                LDS32(al[mt][0], sAl + r0);
                LDS32(al[mt][1], sAl + r1);
                LDS32(al[mt][2], sAl + r0 + 16);
                LDS32(al[mt][3], sAl + r1 + 16);
            }
#pragma unroll
            for (int mt = 0; mt < 4; mt++)
#pragma unroll
                for (int nt = 0; nt < 4; nt++) {
                    MMA_BF16(acc[mt][nt], ah[mt], bh[nt]);
                    MMA_BF16(acc[mt][nt], ah[mt], bl[nt]);
                    MMA_BF16(acc[mt][nt], al[mt], bh[nt]);
                }
        }
        __syncthreads();
    }

    // ---- epilogue: add bias, store
#pragma unroll
    for (int mt = 0; mt < 4; mt++) {
        const int row0 = m0 + wm * 64 + mt * 16 + g;
#pragma unroll
        for (int nt = 0; nt < 4; nt++) {
            const int col = n0 + wn * 32 + nt * 8 + tig * 2;
            const float b0 = bias[col], b1 = bias[col + 1];
            float2 v0 = make_float2(acc[mt][nt][0] + b0, acc[mt][nt][1] + b1);
            float2 v1 = make_float2(acc[mt][nt][2] + b0, acc[mt][nt][3] + b1);
            *(float2*)&C[(size_t)row0 * N + col]       = v0;
            *(float2*)&C[(size_t)(row0 + 8) * N + col] = v1;
        }
    }
}

// ---------------------------------------------------------------------------
// RoPE on q,k halves of qkv (in place), folds q scale.
// ---------------------------------------------------------------------------
__global__ void rope_kernel(float* __restrict__ qkv,
                            const float* __restrict__ cosb,
                            const float* __restrict__ sinb) {
    int idx = blockIdx.x * blockDim.x + threadIdx.x;
    const int total = S_LEN * NHEAD * (HDIM / 2);
    if (idx >= total) return;
    int s   = idx / (NHEAD * (HDIM / 2));
    int rem = idx % (NHEAD * (HDIM / 2));
    int h   = rem / (HDIM / 2);
    int d   = rem % (HDIM / 2);

    const float scale = rsqrtf((float)HDIM);

    float c1 = cosb[s * HDIM + d];
    float s1 = sinb[s * HDIM + d];
    float c2 = cosb[s * HDIM + d + 40];
    float s2 = sinb[s * HDIM + d + 40];

    size_t base = (size_t)s * QKV_N + h * HDIM + d;
    float q1 = qkv[base];
    float q2 = qkv[base + 40];
    qkv[base]      = (q1 * c1 - q2 * s1) * scale;
    qkv[base + 40] = (q2 * c2 + q1 * s2) * scale;
    float k1 = qkv[base + HID];
    float k2 = qkv[base + HID + 40];
    qkv[base + HID]      = k1 * c1 - k2 * s1;
    qkv[base + HID + 40] = k2 * c2 + k1 * s2;
}

// ---------------------------------------------------------------------------
// Block-diagonal attention (fp32). grid = (4 qtiles, 8 segs, 16 heads).
// ---------------------------------------------------------------------------
#define QT     64
#define SQ_LD  81
#define SS_LD  257
#define ATTN_SMEM ((QT*SQ_LD + SEG*SQ_LD + QT*SS_LD) * 4)

__global__ __launch_bounds__(256, 1)
void attn_kernel(const float* __restrict__ qkv,
                 const int* __restrict__ cu,
                 float* __restrict__ out) {
    extern __shared__ float sm[];
    float* sQ = sm;
    float* sK = sQ + QT * SQ_LD;
    float* sS = sK + SEG * SQ_LD;

    const int tid  = threadIdx.x;
    const int qt   = blockIdx.x;
    const int seg  = blockIdx.y;
    const int head = blockIdx.z;

    const int segStart = cu[seg];
    const int q0 = segStart + qt * QT;

    for (int i = tid; i < QT * HDIM; i += 256) {
        int r = i / HDIM, d = i % HDIM;
        sQ[r * SQ_LD + d] = qkv[(size_t)(q0 + r) * QKV_N + head * HDIM + d];
    }
    for (int i = tid; i < SEG * HDIM; i += 256) {
        int r = i / HDIM, d = i % HDIM;
        sK[r * SQ_LD + d] = qkv[(size_t)(segStart + r) * QKV_N + HID + head * HDIM + d];
    }
    __syncthreads();

    const int ti = tid >> 4;
    const int tj = tid & 15;

    {
        float acc[4][16];
#pragma unroll
        for (int a = 0; a < 4; a++)
#pragma unroll
            for (int b = 0; b < 16; b++) acc[a][b] = 0.f;

        for (int d = 0; d < HDIM; d++) {
            float qr[4];
#pragma unroll
            for (int a = 0; a < 4; a++) qr[a] = sQ[(ti * 4 + a) * SQ_LD + d];
            float kr[16];
#pragma unroll
            for (int b = 0; b < 16; b++) kr[b] = sK[(tj + 16 * b) * SQ_LD + d];
#pragma unroll
            for (int a = 0; a < 4; a++)
#pragma unroll
                for (int b = 0; b < 16; b++) acc[a][b] += qr[a] * kr[b];
        }
#pragma unroll
        for (int a = 0; a < 4; a++)
#pragma unroll
            for (int b = 0; b < 16; b++)
                sS[(ti * 4 + a) * SS_LD + tj + 16 * b] = acc[a][b];
    }
    __syncthreads();

    for (int i = tid; i < SEG * HDIM; i += 256) {
        int r = i / HDIM, d = i % HDIM;
        sK[r * SQ_LD + d] = qkv[(size_t)(segStart + r) * QKV_N + 2 * HID + head * HDIM + d];
    }

    {
        const int r  = tid >> 2;
        const int cl = tid & 3;
        float mx = -1e30f;
#pragma unroll
        for (int j = 0; j < 64; j++) {
            float v = sS[r * SS_LD + cl + 4 * j];
            mx = fmaxf(mx, v);
        }
        mx = fmaxf(mx, __shfl_xor_sync(0xFFFFFFFFu, mx, 1));
        mx = fmaxf(mx, __shfl_xor_sync(0xFFFFFFFFu, mx, 2));
        float sum = 0.f;
#pragma unroll
        for (int j = 0; j < 64; j++) {
            int c = cl + 4 * j;
            float e = __expf(sS[r * SS_LD + c] - mx);
            sS[r * SS_LD + c] = e;
            sum += e;
        }
        sum += __shfl_xor_sync(0xFFFFFFFFu, sum, 1);
        sum += __shfl_xor_sync(0xFFFFFFFFu, sum, 2);
        float inv = 1.f / sum;
#pragma unroll
        for (int j = 0; j < 64; j++) sS[r * SS_LD + cl + 4 * j] *= inv;
    }
    __syncthreads();

    {
        float acc[4][5];
#pragma unroll
        for (int a = 0; a < 4; a++)
#pragma unroll
            for (int u = 0; u < 5; u++) acc[a][u] = 0.f;

        for (int c = 0; c < SEG; c++) {
            float wv[4];
#pragma unroll
            for (int a = 0; a < 4; a++) wv[a] = sS[(ti * 4 + a) * SS_LD + c];
            float vr[5];
#pragma unroll
            for (int u = 0; u < 5; u++) vr[u] = sK[c * SQ_LD + tj + 16 * u];
#pragma unroll
            for (int a = 0; a < 4; a++)
#pragma unroll
                for (int u = 0; u < 5; u++) acc[a][u] += wv[a] * vr[u];
        }
#pragma unroll
        for (int a = 0; a < 4; a++) {
            int row = q0 + ti * 4 + a;
#pragma unroll
            for (int u = 0; u < 5; u++) {
                int d = tj + 16 * u;
                out[(size_t)row * HID + head * HDIM + d] = acc[a][u];
            }
        }
    }
}

// ---------------------------------------------------------------------------
extern "C" void kernel_launch(void* const* d_in, const int* in_sizes, int n_in,
                              void* d_out, int out_size) {
    const float* x      = (const float*)d_in[0];
    const float* cosb   = (const float*)d_in[1];
    const float* sinb   = (const float*)d_in[2];
    const float* W_qkv  = (const float*)d_in[3];
    const float* b_qkv  = (const float*)d_in[4];
    const float* W_out  = (const float*)d_in[5];
    const float* b_out  = (const float*)d_in[6];
    const int*   cu     = (const int*)d_in[7];
    float*       outp   = (float*)d_out;

    float *qkv, *attn;
    __nv_bfloat16 *xh, *xl, *ah, *al, *wqh, *wql, *woh, *wol;
    cudaGetSymbolAddress((void**)&qkv,  g_qkv);
    cudaGetSymbolAddress((void**)&attn, g_attn);
    cudaGetSymbolAddress((void**)&xh,   g_xh);
    cudaGetSymbolAddress((void**)&xl,   g_xl);
    cudaGetSymbolAddress((void**)&ah,   g_ah);
    cudaGetSymbolAddress((void**)&al,   g_al);
    cudaGetSymbolAddress((void**)&wqh,  g_wqh);
    cudaGetSymbolAddress((void**)&wql,  g_wql);
    cudaGetSymbolAddress((void**)&woh,  g_woh);
    cudaGetSymbolAddress((void**)&wol,  g_wol);

    static bool attr_set = false;
    if (!attr_set) {
        cudaFuncSetAttribute(attn_kernel,
                             cudaFuncAttributeMaxDynamicSharedMemorySize, ATTN_SMEM);
        cudaFuncSetAttribute(gemm_bf16x3_kernel,
                             cudaFuncAttributeMaxDynamicSharedMemorySize, G_SMEM);
        attr_set = true;
    }

    // 0. splits / weight transposes
    {
        int n = S_LEN * HID;
        split_kernel<<<(n + 255) / 256, 256>>>(x, xh, xl, n);
        dim3 tb(32, 8);
        transpose_split_kernel<<<dim3(QKV_N / 32, HID / 32), tb>>>(W_qkv, wqh, wql, HID, QKV_N);
        transpose_split_kernel<<<dim3(HID / 32, HID / 32), tb>>>(W_out, woh, wol, HID, HID);
    }
    // 1. QKV projection: [2048,1280] @ [1280,3840]^T(view) + b
    gemm_bf16x3_kernel<<<dim3(QKV_N / 128, S_LEN / 128), 256, G_SMEM>>>(
        S_LEN, QKV_N, HID, xh, xl, wqh, wql, b_qkv, qkv);
    // 2. RoPE
    {
        int total = S_LEN * NHEAD * (HDIM / 2);
        rope_kernel<<<(total + 255) / 256, 256>>>(qkv, cosb, sinb);
    }
    // 3. Block-diagonal attention
    attn_kernel<<<dim3(SEG / QT, NSEG, NHEAD), 256, ATTN_SMEM>>>(qkv, cu, attn);
    // 4. split attn output, then out projection
    {
        int n = S_LEN * HID;
        split_kernel<<<(n + 255) / 256, 256>>>(attn, ah, al, n);
    }
    gemm_bf16x3_kernel<<<dim3(HID / 128, S_LEN / 128), 256, G_SMEM>>>(
        S_LEN, HID, HID, ah, al, woh, wol, b_out, outp);
}

// round 4
// speedup vs baseline: 1.8235x; 1.0449x over previous
#include <cuda_runtime.h>
#include <cuda_bf16.h>
#include <cstdint>
#include <math.h>

// ===========================================================================
// VisionAttention (sm_103): bf16-split HMMA GEMMs (ldmatrix, 2 CTA/SM)
//                          + vectorized fp32 block-diag attention
// ===========================================================================

#define S_LEN 2048
#define HID   1280
#define NHEAD 16
#define HDIM  80
#define QKV_N (3 * HID)   // 3840
#define SEG   256
#define NSEG  8

// ---------------- device scratch ----------------
__device__ __align__(256) float g_qkv[S_LEN * QKV_N];
__device__ __align__(256) __nv_bfloat16 g_xh[S_LEN * HID];
__device__ __align__(256) __nv_bfloat16 g_xl[S_LEN * HID];
__device__ __align__(256) __nv_bfloat16 g_ah[S_LEN * HID];
__device__ __align__(256) __nv_bfloat16 g_al[S_LEN * HID];
__device__ __align__(256) __nv_bfloat16 g_wqh[QKV_N * HID];  // [N][K]
__device__ __align__(256) __nv_bfloat16 g_wql[QKV_N * HID];
__device__ __align__(256) __nv_bfloat16 g_woh[HID * HID];
__device__ __align__(256) __nv_bfloat16 g_wol[HID * HID];

__device__ __forceinline__ uint32_t smem_to_u32(const void* p) {
    uint32_t a;
    asm("{ .reg .u64 t; cvta.to.shared.u64 t, %1; cvt.u32.u64 %0, t; }"
        : "=r"(a) : "l"(p));
    return a;
}

#define CP_ASYNC16(sa, gp) \
    asm volatile("cp.async.cg.shared.global [%0], [%1], 16;" \
        :: "r"(sa), "l"(gp) : "memory")
#define CP_COMMIT() asm volatile("cp.async.commit_group;" ::: "memory")

#define MMA_BF16(ac, a, b) \
    asm volatile("mma.sync.aligned.m16n8k16.row.col.f32.bf16.bf16.f32 " \
        "{%0,%1,%2,%3},{%4,%5,%6,%7},{%8,%9},{%0,%1,%2,%3};" \
        : "+f"((ac)[0]), "+f"((ac)[1]), "+f"((ac)[2]), "+f"((ac)[3]) \
        : "r"((a)[0]), "r"((a)[1]), "r"((a)[2]), "r"((a)[3]), \
          "r"((b)[0]), "r"((b)[1]))

#define LDSM_X4(r0, r1, r2, r3, addr) \
    asm volatile("ldmatrix.sync.aligned.m8n8.x4.shared.b16 {%0,%1,%2,%3}, [%4];" \
        : "=r"(r0), "=r"(r1), "=r"(r2), "=r"(r3) : "r"(addr))

// ---------------------------------------------------------------------------
// Prep kernels
// ---------------------------------------------------------------------------
__global__ void split_kernel(const float* __restrict__ src,
                             __nv_bfloat16* __restrict__ hi,
                             __nv_bfloat16* __restrict__ lo, int n) {
    int i = blockIdx.x * blockDim.x + threadIdx.x;
    if (i >= n) return;
    float a = src[i];
    __nv_bfloat16 h = __float2bfloat16(a);
    hi[i] = h;
    lo[i] = __float2bfloat16(a - __bfloat162float(h));
}

// W [K][N] fp32 -> Th, Tl [N][K] bf16
__global__ void transpose_split_kernel(const float* __restrict__ W,
                                       __nv_bfloat16* __restrict__ Th,
                                       __nv_bfloat16* __restrict__ Tl,
                                       int K, int N) {
    __shared__ float t[32][33];
    int bn = blockIdx.x, bk = blockIdx.y;
    int tx = threadIdx.x, ty = threadIdx.y;   // 32 x 8
#pragma unroll
    for (int i = 0; i < 4; i++)
        t[ty + i * 8][tx] = W[(size_t)(bk * 32 + ty + i * 8) * N + bn * 32 + tx];
    __syncthreads();
#pragma unroll
    for (int i = 0; i < 4; i++) {
        float a = t[tx][ty + i * 8];
        __nv_bfloat16 h = __float2bfloat16(a);
        size_t o = (size_t)(bn * 32 + ty + i * 8) * K + bk * 32 + tx;
        Th[o] = h;
        Tl[o] = __float2bfloat16(a - __bfloat162float(h));
    }
}

// ---------------------------------------------------------------------------
// bf16-split GEMM (3 products), ldmatrix fragments, 2 CTA/SM.
// C[M,N] = (Ah+Al)@(Bh+Bl)^T + bias, B given [N][K]. 128x128 tile, BK=32.
// ---------------------------------------------------------------------------
#define GBK        32
#define ROW_B      80
#define TILE_B     (128 * ROW_B)            // 10240
#define STAGE_B    (4 * TILE_B)             // 40960
#define G_SMEM     (2 * STAGE_B)            // 81920

__global__ __launch_bounds__(256, 2)
void gemm_bf16x3_kernel(int M, int N, int K,
                        const __nv_bfloat16* __restrict__ Ah,
                        const __nv_bfloat16* __restrict__ Al,
                        const __nv_bfloat16* __restrict__ Bh,
                        const __nv_bfloat16* __restrict__ Bl,
                        const float* __restrict__ bias,
                        float* __restrict__ C) {
    extern __shared__ __align__(16) char smem[];
    const uint32_t sbase = smem_to_u32(smem);

    const int tid  = threadIdx.x;
    const int wid  = tid >> 5;
    const int lane = tid & 31;
    const int g    = lane >> 2;
    const int tig  = lane & 3;
    const int wm   = wid & 1;         // warp row (64 rows)
    const int wn   = wid >> 1;        // warp col (32 cols)
    const int n0   = blockIdx.x * 128;
    const int m0   = blockIdx.y * 128;

    const __nv_bfloat16* srcs[4] = {
        Ah + (size_t)m0 * K, Al + (size_t)m0 * K,
        Bh + (size_t)n0 * K, Bl + (size_t)n0 * K };

    float acc[4][4][4];
#pragma unroll
    for (int i = 0; i < 4; i++)
#pragma unroll
        for (int j = 0; j < 4; j++)
#pragma unroll
            for (int r = 0; r < 4; r++) acc[i][j][r] = 0.f;

    const int KT = K / GBK;

    auto issue_stage = [&](int buf, int kt) {
#pragma unroll
        for (int i = 0; i < 8; i++) {
            int c    = tid + i * 256;
            int tile = c >> 9;
            int rem  = c & 511;
            int row  = rem >> 2;
            int c16  = rem & 3;
            const __nv_bfloat16* gp = srcs[tile] + (size_t)row * K + kt * GBK + c16 * 8;
            uint32_t sa = sbase + buf * STAGE_B + tile * TILE_B + row * ROW_B + c16 * 16;
            CP_ASYNC16(sa, gp);
        }
        CP_COMMIT();
    };

    // ldmatrix base offsets (per thread, within a stage)
    const uint32_t aOff = (uint32_t)(wm * 64 + (lane & 15)) * ROW_B + ((lane >> 4) & 1) * 16;
    const uint32_t bOff = (uint32_t)(wn * 32 + (lane & 15)) * ROW_B + ((lane >> 4) & 1) * 16;

    issue_stage(0, 0);

    for (int kt = 0; kt < KT; kt++) {
        const int buf = kt & 1;
        if (kt + 1 < KT) {
            issue_stage(buf ^ 1, kt + 1);
            asm volatile("cp.async.wait_group 1;" ::: "memory");
        } else {
            asm volatile("cp.async.wait_group 0;" ::: "memory");
        }
        __syncthreads();

        const uint32_t stage = sbase + buf * STAGE_B;
        const uint32_t aAh = stage + aOff;               // tile 0
        const uint32_t aAl = aAh + TILE_B;               // tile 1
        const uint32_t aBh = stage + 2 * TILE_B + bOff;  // tile 2
        const uint32_t aBl = aBh + TILE_B;               // tile 3

#pragma unroll
        for (int ks = 0; ks < 2; ks++) {
            const uint32_t ko = ks * 32;
            uint32_t bh[4][2], bl[4][2];
#pragma unroll
            for (int np = 0; np < 2; np++) {
                LDSM_X4(bh[np*2][0], bh[np*2+1][0], bh[np*2][1], bh[np*2+1][1],
                        aBh + np * (16 * ROW_B) + ko);
                LDSM_X4(bl[np*2][0], bl[np*2+1][0], bl[np*2][1], bl[np*2+1][1],
                        aBl + np * (16 * ROW_B) + ko);
            }
            uint32_t ah[4][4], al[4][4];
#pragma unroll
            for (int mt = 0; mt < 4; mt++) {
                LDSM_X4(ah[mt][0], ah[mt][1], ah[mt][2], ah[mt][3],
                        aAh + mt * (16 * ROW_B) + ko);
                LDSM_X4(al[mt][0], al[mt][1], al[mt][2], al[mt][3],
                        aAl + mt * (16 * ROW_B) + ko);
            }
#pragma unroll
            for (int mt = 0; mt < 4; mt++)
#pragma unroll
                for (int nt = 0; nt < 4; nt++) {
                    MMA_BF16(acc[mt][nt], ah[mt], bh[nt]);
                    MMA_BF16(acc[mt][nt], ah[mt], bl[nt]);
                    MMA_BF16(acc[mt][nt], al[mt], bh[nt]);
                }
        }
        __syncthreads();
    }

#pragma unroll
    for (int mt = 0; mt < 4; mt++) {
        const int row0 = m0 + wm * 64 + mt * 16 + g;
#pragma unroll
        for (int nt = 0; nt < 4; nt++) {
            const int col = n0 + wn * 32 + nt * 8 + tig * 2;
            const float b0 = bias[col], b1 = bias[col + 1];
            float2 v0 = make_float2(acc[mt][nt][0] + b0, acc[mt][nt][1] + b1);
            float2 v1 = make_float2(acc[mt][nt][2] + b0, acc[mt][nt][3] + b1);
            *(float2*)&C[(size_t)row0 * N + col]       = v0;
            *(float2*)&C[(size_t)(row0 + 8) * N + col] = v1;
        }
    }
}

// ---------------------------------------------------------------------------
// RoPE (in place, folds q scale).
// ---------------------------------------------------------------------------
__global__ void rope_kernel(float* __restrict__ qkv,
                            const float* __restrict__ cosb,
                            const float* __restrict__ sinb) {
    int idx = blockIdx.x * blockDim.x + threadIdx.x;
    const int total = S_LEN * NHEAD * (HDIM / 2);
    if (idx >= total) return;
    int s   = idx / (NHEAD * (HDIM / 2));
    int rem = idx % (NHEAD * (HDIM / 2));
    int h   = rem / (HDIM / 2);
    int d   = rem % (HDIM / 2);

    const float scale = rsqrtf((float)HDIM);

    float c1 = cosb[s * HDIM + d];
    float s1 = sinb[s * HDIM + d];
    float c2 = cosb[s * HDIM + d + 40];
    float s2 = sinb[s * HDIM + d + 40];

    size_t base = (size_t)s * QKV_N + h * HDIM + d;
    float q1 = qkv[base];
    float q2 = qkv[base + 40];
    qkv[base]      = (q1 * c1 - q2 * s1) * scale;
    qkv[base + 40] = (q2 * c2 + q1 * s2) * scale;
    float k1 = qkv[base + HID];
    float k2 = qkv[base + HID + 40];
    qkv[base + HID]      = k1 * c1 - k2 * s1;
    qkv[base + HID + 40] = k2 * c2 + k1 * s2;
}

// ---------------------------------------------------------------------------
// Block-diagonal attention, float4 smem phases, bf16-split epilogue.
// grid = (4 qtiles, 8 segs, 16 heads), 256 threads.
// ---------------------------------------------------------------------------
#define QT     64
#define SQ_LD  88     // floats per row (80 data + 8 pad); conflict-free f4
#define SS_LD  260
#define ATTN_SMEM ((QT*SQ_LD + SEG*SQ_LD + QT*SS_LD) * 4)

__global__ __launch_bounds__(256, 1)
void attn_kernel(const float* __restrict__ qkv,
                 const int* __restrict__ cu,
                 __nv_bfloat16* __restrict__ oh,
                 __nv_bfloat16* __restrict__ ol) {
    extern __shared__ float sm[];
    float* sQ = sm;
    float* sK = sQ + QT * SQ_LD;
    float* sS = sK + SEG * SQ_LD;

    const int tid  = threadIdx.x;
    const int qt   = blockIdx.x;
    const int seg  = blockIdx.y;
    const int head = blockIdx.z;

    const int segStart = cu[seg];
    const int q0 = segStart + qt * QT;

    // load Q (vectorized): 64 rows x 20 float4
    for (int i = tid; i < QT * 20; i += 256) {
        int r = i / 20, d4 = i % 20;
        *(float4*)&sQ[r * SQ_LD + d4 * 4] =
            *(const float4*)&qkv[(size_t)(q0 + r) * QKV_N + head * HDIM + d4 * 4];
    }
    // load K: 256 rows x 20 float4
    for (int i = tid; i < SEG * 20; i += 256) {
        int r = i / 20, d4 = i % 20;
        *(float4*)&sK[r * SQ_LD + d4 * 4] =
            *(const float4*)&qkv[(size_t)(segStart + r) * QKV_N + HID + head * HDIM + d4 * 4];
    }
    __syncthreads();

    const int ti = tid >> 4;   // 0..15
    const int tj = tid & 15;   // 0..15

    // ---- phase 1: scores = Q @ K^T
    {
        float acc[4][16];
#pragma unroll
        for (int a = 0; a < 4; a++)
#pragma unroll
            for (int b = 0; b < 16; b++) acc[a][b] = 0.f;

        for (int d4 = 0; d4 < 20; d4++) {
            float4 qr[4];
#pragma unroll
            for (int a = 0; a < 4; a++)
                qr[a] = *(const float4*)&sQ[(ti * 4 + a) * SQ_LD + d4 * 4];
#pragma unroll
            for (int b = 0; b < 16; b++) {
                float4 kv = *(const float4*)&sK[(tj + 16 * b) * SQ_LD + d4 * 4];
#pragma unroll
                for (int a = 0; a < 4; a++) {
                    acc[a][b] = fmaf(qr[a].x, kv.x, acc[a][b]);
                    acc[a][b] = fmaf(qr[a].y, kv.y, acc[a][b]);
                    acc[a][b] = fmaf(qr[a].z, kv.z, acc[a][b]);
                    acc[a][b] = fmaf(qr[a].w, kv.w, acc[a][b]);
                }
            }
        }
#pragma unroll
        for (int a = 0; a < 4; a++)
#pragma unroll
            for (int b = 0; b < 16; b++)
                sS[(ti * 4 + a) * SS_LD + tj + 16 * b] = acc[a][b];
    }
    __syncthreads();

    // reload V into K buffer
    for (int i = tid; i < SEG * 20; i += 256) {
        int r = i / 20, d4 = i % 20;
        *(float4*)&sK[r * SQ_LD + d4 * 4] =
            *(const float4*)&qkv[(size_t)(segStart + r) * QKV_N + 2 * HID + head * HDIM + d4 * 4];
    }

    // ---- softmax: 4 lanes per row
    {
        const int r  = tid >> 2;
        const int cl = tid & 3;
        float mx = -1e30f;
#pragma unroll
        for (int j = 0; j < 64; j++)
            mx = fmaxf(mx, sS[r * SS_LD + cl + 4 * j]);
        mx = fmaxf(mx, __shfl_xor_sync(0xFFFFFFFFu, mx, 1));
        mx = fmaxf(mx, __shfl_xor_sync(0xFFFFFFFFu, mx, 2));
        float sum = 0.f;
#pragma unroll
        for (int j = 0; j < 64; j++) {
            int c = cl + 4 * j;
            float e = __expf(sS[r * SS_LD + c] - mx);
            sS[r * SS_LD + c] = e;
            sum += e;
        }
        sum += __shfl_xor_sync(0xFFFFFFFFu, sum, 1);
        sum += __shfl_xor_sync(0xFFFFFFFFu, sum, 2);
        float inv = 1.f / sum;
#pragma unroll
        for (int j = 0; j < 64; j++) sS[r * SS_LD + cl + 4 * j] *= inv;
    }
    __syncthreads();

    // ---- phase 2: out = P @ V, epilogue splits to bf16 hi/lo
    {
        float acc[4][5];
#pragma unroll
        for (int a = 0; a < 4; a++)
#pragma unroll
            for (int u = 0; u < 5; u++) acc[a][u] = 0.f;

        for (int c4 = 0; c4 < 64; c4++) {
            float4 wv[4];
#pragma unroll
            for (int a = 0; a < 4; a++)
                wv[a] = *(const float4*)&sS[(ti * 4 + a) * SS_LD + c4 * 4];
#pragma unroll
            for (int cc = 0; cc < 4; cc++) {
                const int c = c4 * 4 + cc;
                float vr[5];
#pragma unroll
                for (int u = 0; u < 5; u++) vr[u] = sK[c * SQ_LD + tj + 16 * u];
                const float w0 = (cc == 0) ? wv[0].x : (cc == 1) ? wv[0].y : (cc == 2) ? wv[0].z : wv[0].w;
                const float w1 = (cc == 0) ? wv[1].x : (cc == 1) ? wv[1].y : (cc == 2) ? wv[1].z : wv[1].w;
                const float w2 = (cc == 0) ? wv[2].x : (cc == 1) ? wv[2].y : (cc == 2) ? wv[2].z : wv[2].w;
                const float w3 = (cc == 0) ? wv[3].x : (cc == 1) ? wv[3].y : (cc == 2) ? wv[3].z : wv[3].w;
#pragma unroll
                for (int u = 0; u < 5; u++) {
                    acc[0][u] = fmaf(w0, vr[u], acc[0][u]);
                    acc[1][u] = fmaf(w1, vr[u], acc[1][u]);
                    acc[2][u] = fmaf(w2, vr[u], acc[2][u]);
                    acc[3][u] = fmaf(w3, vr[u], acc[3][u]);
                }
            }
        }
#pragma unroll
        for (int a = 0; a < 4; a++) {
            const int row = q0 + ti * 4 + a;
#pragma unroll
            for (int u = 0; u < 5; u++) {
                const int d = tj + 16 * u;
                const size_t o = (size_t)row * HID + head * HDIM + d;
                float v = acc[a][u];
                __nv_bfloat16 h = __float2bfloat16(v);
                oh[o] = h;
                ol[o] = __float2bfloat16(v - __bfloat162float(h));
            }
        }
    }
}

// ---------------------------------------------------------------------------
extern "C" void kernel_launch(void* const* d_in, const int* in_sizes, int n_in,
                              void* d_out, int out_size) {
    const float* x      = (const float*)d_in[0];
    const float* cosb   = (const float*)d_in[1];
    const float* sinb   = (const float*)d_in[2];
    const float* W_qkv  = (const float*)d_in[3];
    const float* b_qkv  = (const float*)d_in[4];
    const float* W_out  = (const float*)d_in[5];
    const float* b_out  = (const float*)d_in[6];
    const int*   cu     = (const int*)d_in[7];
    float*       outp   = (float*)d_out;

    float* qkv;
    __nv_bfloat16 *xh, *xl, *ah, *al, *wqh, *wql, *woh, *wol;
    cudaGetSymbolAddress((void**)&qkv,  g_qkv);
    cudaGetSymbolAddress((void**)&xh,   g_xh);
    cudaGetSymbolAddress((void**)&xl,   g_xl);
    cudaGetSymbolAddress((void**)&ah,   g_ah);
    cudaGetSymbolAddress((void**)&al,   g_al);
    cudaGetSymbolAddress((void**)&wqh,  g_wqh);
    cudaGetSymbolAddress((void**)&wql,  g_wql);
    cudaGetSymbolAddress((void**)&woh,  g_woh);
    cudaGetSymbolAddress((void**)&wol,  g_wol);

    static bool attr_set = false;
    if (!attr_set) {
        cudaFuncSetAttribute(attn_kernel,
                             cudaFuncAttributeMaxDynamicSharedMemorySize, ATTN_SMEM);
        cudaFuncSetAttribute(gemm_bf16x3_kernel,
                             cudaFuncAttributeMaxDynamicSharedMemorySize, G_SMEM);
        attr_set = true;
    }

    // 0. prep
    {
        int n = S_LEN * HID;
        split_kernel<<<(n + 255) / 256, 256>>>(x, xh, xl, n);
        dim3 tb(32, 8);
        transpose_split_kernel<<<dim3(QKV_N / 32, HID / 32), tb>>>(W_qkv, wqh, wql, HID, QKV_N);
        transpose_split_kernel<<<dim3(HID / 32, HID / 32), tb>>>(W_out, woh, wol, HID, HID);
    }
    // 1. QKV projection
    gemm_bf16x3_kernel<<<dim3(QKV_N / 128, S_LEN / 128), 256, G_SMEM>>>(
        S_LEN, QKV_N, HID, xh, xl, wqh, wql, b_qkv, qkv);
    // 2. RoPE
    {
        int total = S_LEN * NHEAD * (HDIM / 2);
        rope_kernel<<<(total + 255) / 256, 256>>>(qkv, cosb, sinb);
    }
    // 3. attention (writes bf16 hi/lo directly)
    attn_kernel<<<dim3(SEG / QT, NSEG, NHEAD), 256, ATTN_SMEM>>>(qkv, cu, ah, al);
    // 4. out projection
    gemm_bf16x3_kernel<<<dim3(HID / 128, S_LEN / 128), 256, G_SMEM>>>(
        S_LEN, HID, HID, ah, al, woh, wol, b_out, outp);
}